// round 3
// baseline (speedup 1.0000x reference)
#include <cuda_runtime.h>
#include <math.h>

// ---------------- problem constants ----------------
#define BATCH 4
#define DD 28
#define HH 28
#define WW 8
#define SP (DD*HH*WW)        // 6272
#define NSP (BATCH*SP)       // 25088 = 196*128
#define CMAX 128
#define DP 30
#define HP 30
#define WP 10
#define PSP (DP*HP*WP)       // 9000

typedef unsigned long long ull;

__device__ __forceinline__ ull pk(float a, float b) {
    ull r; asm("mov.b64 %0,{%1,%2};" : "=l"(r) : "f"(a), "f"(b)); return r;
}
__device__ __forceinline__ void upk(ull v, float& a, float& b) {
    asm("mov.b64 {%0,%1},%2;" : "=f"(a), "=f"(b) : "l"(v));
}
__device__ __forceinline__ ull ff2(ull a, ull b, ull c) {
    ull d; asm("fma.rn.f32x2 %0,%1,%2,%3;" : "=l"(d) : "l"(a), "l"(b), "l"(c)); return d;
}

// ---------------- scratch ----------------
__device__ float g_bufA[BATCH*SP*CMAX];
__device__ float g_bufB[BATCH*SP*CMAX];
__device__ float g_bufP[BATCH*PSP*CMAX];
__device__ float2 g_wpair[557280];
__device__ float  g_wdef[27*128*128];
__device__ float4 g_meta[27*NSP];
__device__ float g_ps[784*CMAX];
__device__ float g_pq[784*CMAX];
__device__ float2 g_bn[4][CMAX];

#define W1_OFF 0
#define W2_OFF 864
#define W3_OFF 56160
#define W4_OFF 277344

#define S1 864
#define S2 55296
#define S3 221184
#define S4 279936
#define S5 442368
#define WT_TOTAL (S1+S2+S3+S4+S5)

// ---------------- merged weight transpose ----------------
__global__ void wtrans_all_kernel(const float* __restrict__ w1, const float* __restrict__ w2,
                                  const float* __restrict__ w3, const float* __restrict__ w4,
                                  const float* __restrict__ w5) {
    int idx = blockIdx.x * blockDim.x + threadIdx.x;
    if (idx >= WT_TOTAL) return;
    const float* src; float2* dst; int CIN, COUT; int l = idx; int plain = 0;
    if (l < S1)              { src = w1; dst = g_wpair + W1_OFF; CIN = 1;   COUT = 32; }
    else if ((l -= S1) < S2) { src = w2; dst = g_wpair + W2_OFF; CIN = 32;  COUT = 64; }
    else if ((l -= S2) < S3) { src = w3; dst = g_wpair + W3_OFF; CIN = 64;  COUT = 128; }
    else if ((l -= S3) < S4) { src = w4; dst = g_wpair + W4_OFF; CIN = 128; COUT = 81; }
    else { l -= S4; src = w5; dst = nullptr; CIN = 128; COUT = 128; plain = 1; }
    int n = l % 27;
    int c = (l / 27) % CIN;
    int o = l / (27 * CIN);
    float v = src[l];
    if (plain) g_wdef[((size_t)n * 128 + c) * 128 + o] = v;
    else       dst[((size_t)n * CIN + c) * COUT + o] = make_float2(v, v);
}

// ---------------- tiled conv3d, channel-last ----------------
// BN_LAYER: -1 = none, else index into g_bn for input transform
template<int CIN, int COUT, bool RELU, bool NCDHW_OUT, int BN_LAYER, bool STATS>
__global__ void conv_cl_kernel(const float* __restrict__ x, const float2* __restrict__ wp,
                               const float* __restrict__ bias, float* __restrict__ y) {
    constexpr int CH = (CIN < 16) ? CIN : 16;
    constexpr int NCH = CIN / CH;
    __shared__ float xs[CH][18][12];

    int tid = threadIdx.x;
    int blk = blockIdx.x;
    int hb = blk % 7;
    int d  = (blk / 7) % DD;
    int b  = blk / (7 * DD);
    int h0 = hb * 4;
    int o  = (tid < COUT) ? tid : 0;

    ull acc2[4][4];
    #pragma unroll
    for (int ph = 0; ph < 4; ph++)
        #pragma unroll
        for (int j = 0; j < 4; j++) acc2[ph][j] = 0ull;

    for (int cc = 0; cc < NCH; cc++) {
        __syncthreads();
        for (int i = tid; i < 180 * CH; i += 128) {
            int ci, pos;
            if (CH == 16) { ci = i & 15; pos = i >> 4; }
            else          { ci = i % CH; pos = i / CH; }
            int zw = pos % 10;
            int zh = (pos / 10) % 6;
            int zd = pos / 60;
            int gd = d + zd - 1, gh = h0 + zh - 1, gw = zw - 1;
            float v = 0.0f;
            int cg = cc * CH + ci;
            if ((unsigned)gd < DD && (unsigned)gh < HH && (unsigned)gw < WW) {
                v = x[((size_t)((b * DD + gd) * HH + gh) * WW + gw) * CIN + cg];
                if (BN_LAYER >= 0) { float2 t = g_bn[BN_LAYER][cg]; v = fmaf(v, t.x, t.y); }
            }
            xs[ci][zd * 6 + zh][zw] = v;
        }
        __syncthreads();

        for (int ci = 0; ci < CH; ci++) {
            int cglob = cc * CH + ci;
            #pragma unroll
            for (int zd = 0; zd < 3; zd++) {
                #pragma unroll
                for (int zh = 0; zh < 6; zh++) {
                    const float2* row = (const float2*)&xs[ci][zd * 6 + zh][0];
                    float2 e0 = row[0], e1 = row[1], e2 = row[2], e3 = row[3], e4 = row[4];
                    ull P[9];
                    P[0] = pk(e0.x, e0.y); P[2] = pk(e1.x, e1.y); P[4] = pk(e2.x, e2.y);
                    P[6] = pk(e3.x, e3.y); P[8] = pk(e4.x, e4.y);
                    P[1] = pk(e0.y, e1.x); P[3] = pk(e1.y, e2.x);
                    P[5] = pk(e2.y, e3.x); P[7] = pk(e3.y, e4.x);
                    #pragma unroll
                    for (int ph = 0; ph < 4; ph++) {
                        int kh1 = zh - ph;
                        if (kh1 < 0 || kh1 > 2) continue;
                        #pragma unroll
                        for (int kw1 = 0; kw1 < 3; kw1++) {
                            int n = zd * 9 + kh1 * 3 + kw1;
                            ull wv2 = *(const ull*)&wp[((size_t)n * CIN + cglob) * COUT + o];
                            #pragma unroll
                            for (int j = 0; j < 4; j++)
                                acc2[ph][j] = ff2(wv2, P[kw1 + 2 * j], acc2[ph][j]);
                        }
                    }
                }
            }
        }
    }

    if (tid < COUT) {
        float bs = bias[o];
        float ssum = 0.f, sq = 0.f;
        #pragma unroll
        for (int ph = 0; ph < 4; ph++) {
            #pragma unroll
            for (int j = 0; j < 4; j++) {
                float v0, v1; upk(acc2[ph][j], v0, v1);
                v0 += bs; v1 += bs;
                if (RELU) { v0 = fmaxf(v0, 0.f); v1 = fmaxf(v1, 0.f); }
                if (STATS) { ssum += v0 + v1; sq += v0 * v0 + v1 * v1; }
                int pw = 2 * j;
                if (NCDHW_OUT) {
                    size_t base = (size_t)(b * COUT + o) * SP + (size_t)(d * HH + h0 + ph) * WW;
                    y[base + pw] = v0; y[base + pw + 1] = v1;
                } else {
                    size_t base = ((size_t)((b * DD + d) * HH + (h0 + ph)) * WW + pw) * COUT + o;
                    y[base] = v0; y[base + COUT] = v1;
                }
            }
        }
        if (STATS) { g_ps[blk * CMAX + o] = ssum; g_pq[blk * CMAX + o] = sq; }
    }
}

// ---------------- BN finalize ----------------
__global__ void bn_fin_kernel(int C, int nblk, const float* __restrict__ gma,
                              const float* __restrict__ bta, int layer) {
    int c = threadIdx.x;
    if (c >= C) return;
    float s = 0.f, q = 0.f;
    for (int i = 0; i < nblk; i++) { s += g_ps[i * CMAX + c]; q += g_pq[i * CMAX + c]; }
    float m = s / (float)NSP;
    float var = q / (float)NSP - m * m;
    float r = rsqrtf(var + 1e-5f);
    float sc = r * gma[c];
    g_bn[layer][c] = make_float2(sc, bta[c] - m * sc);
}

// ---------------- BN3 into padded channel-last buffer ----------------
__global__ void pad_apply_kernel(const float* __restrict__ src) {
    int idx = blockIdx.x * blockDim.x + threadIdx.x;
    if (idx >= NSP * CMAX) return;
    int c = idx & 127;
    int s = idx >> 7;
    int w = s & 7;
    int t = s >> 3;
    int h = t % HH; t /= HH;
    int d = t % DD;
    int b = t / DD;
    float2 bn = g_bn[2][c];
    size_t dst = ((size_t)((b * DP + d + 1) * HP + h + 1) * WP + (w + 1)) * CMAX + c;
    g_bufP[dst] = fmaf(src[idx], bn.x, bn.y);
}

// ---------------- sampling metadata ----------------
__global__ void meta_kernel(const float* __restrict__ off) {
    int idx = blockIdx.x * blockDim.x + threadIdx.x;
    if (idx >= 27 * NSP) return;
    int n = idx / NSP;
    int s = idx - n * NSP;
    int w = s & 7;
    int t = s >> 3;
    int h = t % HH; t /= HH;
    int d = t % DD;
    int b = t / DD;
    int kd = n / 9 - 1, kh = (n / 3) % 3 - 1, kw = n % 3 - 1;
    size_t obase = (size_t)b * 81 * SP + (size_t)((d * HH + h) * WW + w);
    float od  = off[obase + (size_t)n * SP];
    float oh  = off[obase + (size_t)(27 + n) * SP];
    float ow_ = off[obase + (size_t)(54 + n) * SP];
    float pd = fminf(fmaxf((float)(d + 1 + kd) + od, 0.f), 29.f);
    float ph = fminf(fmaxf((float)(h + 1 + kh) + oh, 0.f), 29.f);
    float pw = fminf(fmaxf((float)(w + 1 + kw) + ow_, 0.f), 9.f);
    float fd = fminf(fmaxf(floorf(pd), 0.f), 28.f);
    float fh = fminf(fmaxf(floorf(ph), 0.f), 28.f);
    float fw = fminf(fmaxf(floorf(pw), 0.f), 8.f);
    float td = fminf(fmaxf(pd - fd, 0.f), 1.f);
    float th = fminf(fmaxf(ph - fh, 0.f), 1.f);
    float tw = fminf(fmaxf(pw - fw, 0.f), 1.f);
    int base = ((b * DP + (int)fd) * HP + (int)fh) * WP + (int)fw;
    g_meta[idx] = make_float4(td, th, tw, __int_as_float(base));
}

// ---------------- deformable conv ----------------
__global__ void __launch_bounds__(128) deform_kernel(const float* __restrict__ db,
                                                     float* __restrict__ y) {
    __shared__ float s_tile[128 * 68];

    int tid = threadIdx.x;
    int posBase = blockIdx.x * 64;

    ull acc2[32];
    #pragma unroll
    for (int j = 0; j < 32; j++) acc2[j] = 0ull;

    for (int n = 0; n < 27; n++) {
        __syncthreads();
        const float4* mrow = g_meta + (size_t)n * NSP + posBase;
        for (int p = 0; p < 64; p++) {
            float4 m = mrow[p];
            int base = __float_as_int(m.w);
            float td = m.x, th = m.y, tw = m.z;
            float ad = 1.f - td, ah = 1.f - th, aw = 1.f - tw;
            float c00 = ad * ah, c01 = ad * th, c10 = td * ah, c11 = td * th;
            const float* ptr = g_bufP + (size_t)base * CMAX + tid;
            float v;
            v  = (c00 * aw) * ptr[0];
            v += (c00 * tw) * ptr[CMAX];
            v += (c01 * aw) * ptr[WP * CMAX];
            v += (c01 * tw) * ptr[(WP + 1) * CMAX];
            v += (c10 * aw) * ptr[HP * WP * CMAX];
            v += (c10 * tw) * ptr[(HP * WP + 1) * CMAX];
            v += (c11 * aw) * ptr[(HP * WP + WP) * CMAX];
            v += (c11 * tw) * ptr[(HP * WP + WP + 1) * CMAX];
            s_tile[tid * 68 + p] = v;
        }
        __syncthreads();

        const float* wrow = g_wdef + (size_t)n * 128 * 128;
        for (int c = 0; c < 128; c++) {
            float wv = wrow[c * 128 + tid];
            ull wv2 = pk(wv, wv);
            const ulonglong2* st2 = (const ulonglong2*)(s_tile + c * 68);
            #pragma unroll
            for (int jj = 0; jj < 16; jj++) {
                ulonglong2 q = st2[jj];
                acc2[2 * jj]     = ff2(wv2, q.x, acc2[2 * jj]);
                acc2[2 * jj + 1] = ff2(wv2, q.y, acc2[2 * jj + 1]);
            }
        }
    }

    float bs = db[tid];
    float ssum = 0.f, sq = 0.f;
    #pragma unroll
    for (int j = 0; j < 32; j++) {
        float v0, v1; upk(acc2[j], v0, v1);
        v0 = fmaxf(v0 + bs, 0.f); v1 = fmaxf(v1 + bs, 0.f);
        ssum += v0 + v1; sq += v0 * v0 + v1 * v1;
        int s0 = posBase + 2 * j;
        y[(size_t)s0 * CMAX + tid]       = v0;
        y[(size_t)(s0 + 1) * CMAX + tid] = v1;
    }
    g_ps[blockIdx.x * CMAX + tid] = ssum;
    g_pq[blockIdx.x * CMAX + tid] = sq;
}

// ---------------- head ----------------
__global__ void head_kernel(const float* __restrict__ y, const float* __restrict__ fcw,
                            const float* __restrict__ fcb, float* __restrict__ out) {
    int b = blockIdx.x;
    int c = threadIdx.x;
    const float* p = y + (size_t)b * SP * CMAX + c;
    float s = 0.f;
    for (int i = 0; i < SP; i++) s += p[(size_t)i * CMAX];
    __shared__ float pooled[128];
    __shared__ float logits[10];
    float2 bn = g_bn[3][c];
    pooled[c] = fmaf(s / (float)SP, bn.x, bn.y);
    __syncthreads();
    if (c < 10) {
        float l = fcb[c];
        for (int k = 0; k < 128; k++) l += pooled[k] * fcw[c * 128 + k];
        logits[c] = l;
    }
    __syncthreads();
    if (c == 0) {
        float mx = logits[0];
        for (int j = 1; j < 10; j++) mx = fmaxf(mx, logits[j]);
        float se = 0.f;
        for (int j = 0; j < 10; j++) se += expf(logits[j] - mx);
        float lse = mx + logf(se);
        for (int j = 0; j < 10; j++) out[b * 10 + j] = logits[j] - lse;
    }
}

// ---------------- launcher ----------------
extern "C" void kernel_launch(void* const* d_in, const int* in_sizes, int n_in,
                              void* d_out, int out_size) {
    const float* x   = (const float*)d_in[0];
    const float* c1w = (const float*)d_in[1];  const float* c1b = (const float*)d_in[2];
    const float* g1  = (const float*)d_in[3];  const float* b1  = (const float*)d_in[4];
    const float* c2w = (const float*)d_in[5];  const float* c2b = (const float*)d_in[6];
    const float* g2  = (const float*)d_in[7];  const float* b2  = (const float*)d_in[8];
    const float* c3w = (const float*)d_in[9];  const float* c3b = (const float*)d_in[10];
    const float* g3  = (const float*)d_in[11]; const float* b3  = (const float*)d_in[12];
    const float* ow  = (const float*)d_in[13]; const float* ob  = (const float*)d_in[14];
    const float* dw  = (const float*)d_in[15]; const float* db  = (const float*)d_in[16];
    const float* g4  = (const float*)d_in[17]; const float* b4  = (const float*)d_in[18];
    const float* fcw = (const float*)d_in[19]; const float* fcb = (const float*)d_in[20];

    float* out = (float*)d_out;
    float* offsets = out + BATCH * 10;

    float *bufA, *bufB, *bufP; float2* wpair;
    cudaGetSymbolAddress((void**)&bufA, g_bufA);
    cudaGetSymbolAddress((void**)&bufB, g_bufB);
    cudaGetSymbolAddress((void**)&bufP, g_bufP);
    cudaGetSymbolAddress((void**)&wpair, g_wpair);

    cudaMemsetAsync(bufP, 0, (size_t)BATCH * PSP * CMAX * sizeof(float));
    wtrans_all_kernel<<<(WT_TOTAL + 255) / 256, 256>>>(c1w, c2w, c3w, ow, dw);

    const int CBLK = BATCH * DD * (HH / 4);   // 784

    conv_cl_kernel<1, 32, true, false, -1, true><<<CBLK, 128>>>(x, wpair + W1_OFF, c1b, bufA);
    bn_fin_kernel<<<1, 128>>>(32, CBLK, g1, b1, 0);

    conv_cl_kernel<32, 64, true, false, 0, true><<<CBLK, 128>>>(bufA, wpair + W2_OFF, c2b, bufB);
    bn_fin_kernel<<<1, 128>>>(64, CBLK, g2, b2, 1);

    conv_cl_kernel<64, 128, true, false, 1, true><<<CBLK, 128>>>(bufB, wpair + W3_OFF, c3b, bufA);
    bn_fin_kernel<<<1, 128>>>(128, CBLK, g3, b3, 2);

    pad_apply_kernel<<<(NSP * CMAX + 255) / 256, 256>>>(bufA);
    conv_cl_kernel<128, 81, false, true, 2, false><<<CBLK, 128>>>(bufA, wpair + W4_OFF, ob, offsets);

    meta_kernel<<<(27 * NSP + 255) / 256, 256>>>(offsets);
    deform_kernel<<<NSP / 64, 128>>>(db, bufB);
    bn_fin_kernel<<<1, 128>>>(128, NSP / 64, g4, b4, 3);

    head_kernel<<<BATCH, 128>>>(bufB, fcw, fcb, out);
}